// round 12
// baseline (speedup 1.0000x reference)
#include <cuda_runtime.h>
#include <cuda_fp16.h>
#include <math.h>
#include <stdint.h>

#define D_MODEL   1024
#define NUM_HEADS 16
#define HEAD_DIM  64
#define BATCH     2
#define SEQ       2048
#define TOKENS    (BATCH * SEQ)      // 4096
#define QSCALE    (0.125f * 1.44269504f)

// ---------------- scratch (device globals; no allocation allowed) ----------
__device__ __align__(16) __half g_qh[TOKENS * D_MODEL];   // [b,h,s,d], pre-scaled
__device__ __align__(16) __half g_kh[TOKENS * D_MODEL];
__device__ __align__(16) __half g_vh[TOKENS * D_MODEL];
__device__ __align__(16) float  g_ct[SEQ * 32];
__device__ __align__(16) float  g_st[SEQ * 32];
__device__ __align__(16) __half g_xh[TOKENS * D_MODEL];
__device__ __align__(16) __half g_wqh[3 * D_MODEL * D_MODEL];
__device__ __align__(16) __half g_woh[D_MODEL * D_MODEL];
__device__ __align__(16) __half g_aoh[TOKENS * D_MODEL];

// ---------------------------------------------------------------------------
// helpers
// ---------------------------------------------------------------------------
__device__ __forceinline__ uint32_t smem_u32(const void* p) {
    uint32_t a;
    asm("{ .reg .u64 t; cvta.to.shared.u64 t, %1; cvt.u32.u64 %0, t; }" : "=r"(a) : "l"(p));
    return a;
}
__device__ __forceinline__ void cp16(uint32_t dst, const void* src) {
    asm volatile("cp.async.cg.shared.global [%0], [%1], 16;" :: "r"(dst), "l"(src));
}
#define CP_COMMIT() asm volatile("cp.async.commit_group;")
#define CP_WAIT(n)  asm volatile("cp.async.wait_group %0;" :: "n"(n))

__device__ __forceinline__ void ldsm4(uint32_t* r, uint32_t a) {
    asm volatile("ldmatrix.sync.aligned.m8n8.x4.shared.b16 {%0,%1,%2,%3}, [%4];"
                 : "=r"(r[0]), "=r"(r[1]), "=r"(r[2]), "=r"(r[3]) : "r"(a));
}
__device__ __forceinline__ void ldsm4t(uint32_t* r, uint32_t a) {
    asm volatile("ldmatrix.sync.aligned.m8n8.x4.trans.shared.b16 {%0,%1,%2,%3}, [%4];"
                 : "=r"(r[0]), "=r"(r[1]), "=r"(r[2]), "=r"(r[3]) : "r"(a));
}
__device__ __forceinline__ void mma_(float* c, const uint32_t* a, const uint32_t* b) {
    asm volatile(
        "mma.sync.aligned.m16n8k16.row.col.f32.f16.f16.f32 "
        "{%0,%1,%2,%3}, {%4,%5,%6,%7}, {%8,%9}, {%0,%1,%2,%3};"
        : "+f"(c[0]), "+f"(c[1]), "+f"(c[2]), "+f"(c[3])
        : "r"(a[0]), "r"(a[1]), "r"(a[2]), "r"(a[3]), "r"(b[0]), "r"(b[1]));
}
__device__ __forceinline__ uint32_t swz(uint32_t o) { return o ^ ((o >> 3) & 0x70); }
__device__ __forceinline__ float ex2(float x) {
    float r; asm("ex2.approx.ftz.f32 %0, %1;" : "=f"(r) : "f"(x)); return r;
}
__device__ __forceinline__ __half2 h2ex2(__half2 x) {
    uint32_t xi = *(uint32_t*)&x, ri;
    asm("ex2.approx.f16x2 %0, %1;" : "=r"(ri) : "r"(xi));
    return *(__half2*)&ri;
}
__device__ __forceinline__ uint32_t h2u(__half2 h) { return *(uint32_t*)&h; }

// ---------------------------------------------------------------------------
// merged fp32 -> fp16 conversion for x, w_qkv, w_o
// ---------------------------------------------------------------------------
#define N4_X  (TOKENS * D_MODEL / 4)
#define N4_WQ (3 * D_MODEL * D_MODEL / 4)
#define N4_WO (D_MODEL * D_MODEL / 4)
#define N4_ALL (N4_X + N4_WQ + N4_WO)

__global__ __launch_bounds__(256) void conv_all_kernel(
    const float* __restrict__ x, const float* __restrict__ wq,
    const float* __restrict__ wo)
{
    int i = blockIdx.x * 256 + threadIdx.x;
    const float* src; __half* dst; int off;
    if (i < N4_X)              { src = x;  dst = g_xh;  off = i; }
    else if (i < N4_X + N4_WQ) { src = wq; dst = g_wqh; off = i - N4_X; }
    else                       { src = wo; dst = g_woh; off = i - N4_X - N4_WQ; }
    float4 v = ((const float4*)src)[off];
    __half2* h2 = (__half2*)dst;
    h2[2 * off]     = __floats2half2_rn(v.x, v.y);
    h2[2 * off + 1] = __floats2half2_rn(v.z, v.w);
}

// ---------------------------------------------------------------------------
// RoPE tables (fp64 trig)
// ---------------------------------------------------------------------------
__global__ void rope_table_kernel(const int* __restrict__ pos)
{
    int idx = blockIdx.x * 256 + threadIdx.x;
    if (idx >= SEQ * 32) return;
    int s = idx >> 5, i = idx & 31;
    double f = (double)pos[s] * pow(10000.0, -(double)i / 32.0);
    g_ct[idx] = (float)cos(f);
    g_st[idx] = (float)sin(f);
}

// ---------------------------------------------------------------------------
// HMMA fp16 NT GEMM: C[M,N] = A[M,K] B[N,K]^T, K=1024, fp32 accum.
// 128x128 tile, BK=64, 8 warps, 3-stage cp.async pipeline, 2 CTAs/SM.
// MODE 0: fp32 C out (smem-staged coalesced stores).
// MODE 1: fused RoPE+split -> g_qh/g_kh/g_vh (smem-staged coalesced stores).
// ---------------------------------------------------------------------------
#define GK 1024
#define STAGE 32768   // A 16K | B 16K
#define NSTG  3

__device__ __forceinline__ void gemm_load_stage(
    uint32_t base, int tid, int m0, int n0, int c0,
    const __half* A, const __half* B)
{
#pragma unroll
    for (int u = 0; u < 4; u++) {
        int idx = u * 256 + tid;          // 0..1023
        int row = idx >> 3, seg = idx & 7;
        uint32_t d = swz((row << 7) + (seg << 4));
        cp16(base + d,         A + (size_t)(m0 + row) * GK + c0 + seg * 8);
        cp16(base + 16384 + d, B + (size_t)(n0 + row) * GK + c0 + seg * 8);
    }
}

template<int MODE>
__global__ __launch_bounds__(256, 2) void gemm_tc(
    const __half* __restrict__ A, const __half* __restrict__ B,
    float* __restrict__ Cout, int N)
{
    extern __shared__ char smraw[];
    const uint32_t sb = smem_u32(smraw);
    const int tid = threadIdx.x;
    const int wid = tid >> 5, lane = tid & 31;
    const int wm = wid & 3, wn = wid >> 2;
    const int m0 = blockIdx.y << 7, n0 = blockIdx.x << 7;

    float acc[2][8][4];
#pragma unroll
    for (int f = 0; f < 2; f++)
#pragma unroll
        for (int j = 0; j < 8; j++)
#pragma unroll
            for (int x = 0; x < 4; x++) acc[f][j][x] = 0.0f;

#pragma unroll
    for (int p = 0; p < NSTG - 1; p++) {
        gemm_load_stage(sb + p * STAGE, tid, m0, n0, p * 64, A, B);
        CP_COMMIT();
    }

    for (int c = 0; c < 16; c++) {
        if (c < 15) CP_WAIT(1); else CP_WAIT(0);
        __syncthreads();
        if (c + NSTG - 1 < 16) {
            gemm_load_stage(sb + ((c + NSTG - 1) % NSTG) * STAGE, tid, m0, n0,
                            (c + NSTG - 1) * 64, A, B);
            CP_COMMIT();
        }
        const uint32_t base = sb + (c % NSTG) * STAGE;

#pragma unroll
        for (int kt = 0; kt < 4; kt++) {
            uint32_t ah[2][4];
#pragma unroll
            for (int f = 0; f < 2; f++) {
                int mrow = wm * 32 + f * 16 + (lane & 7) + ((lane >> 3) & 1) * 8;
                ldsm4(ah[f], base + swz((mrow << 7) + kt * 32 + ((lane >> 4) << 4)));
            }
            uint32_t bh[8][2];
#pragma unroll
            for (int f = 0; f < 4; f++) {
                int nrow = wn * 64 + f * 16 + (lane & 7) + ((lane >> 4) & 1) * 8;
                uint32_t r[4];
                ldsm4(r, base + 16384 +
                         swz((nrow << 7) + kt * 32 + (((lane >> 3) & 1) << 4)));
                bh[2 * f][0] = r[0]; bh[2 * f][1] = r[1];
                bh[2 * f + 1][0] = r[2]; bh[2 * f + 1][1] = r[3];
            }
#pragma unroll
            for (int f = 0; f < 2; f++)
#pragma unroll
                for (int j = 0; j < 8; j++) mma_(acc[f][j], ah[f], bh[j]);
        }
    }

    const int g = lane >> 2, i2 = (lane & 3) * 2;
    __syncthreads();    // all warps done with stage smem; reuse for epilogue

    if (MODE == 0) {
        // stage fp32 tile (padded rows: 132 floats, conflict-free)
        float* cs = (float*)smraw;
#pragma unroll
        for (int f = 0; f < 2; f++)
#pragma unroll
            for (int j = 0; j < 8; j++) {
                int row_l = wm * 32 + f * 16 + g;
                int col_l = wn * 64 + j * 8 + i2;
                *(float2*)&cs[row_l * 132 + col_l] =
                    make_float2(acc[f][j][0], acc[f][j][1]);
                *(float2*)&cs[(row_l + 8) * 132 + col_l] =
                    make_float2(acc[f][j][2], acc[f][j][3]);
            }
        __syncthreads();
#pragma unroll
        for (int it = 0; it < 16; it++) {
            int row = it * 8 + wid;
            float4 v = *(float4*)&cs[row * 132 + lane * 4];
            *(float4*)&Cout[(size_t)(m0 + row) * N + n0 + lane * 4] = v;
        }
    } else {
        // fused RoPE + head-split; stage fp16 tile (padded rows: 136 halves)
        __half* hs = (__half*)smraw;
        const int sel = n0 >> 10;            // 0=q, 1=k, 2=v
        const int cb  = n0 & 1023;           // section-local tile base (128-aligned)
#pragma unroll
        for (int f = 0; f < 2; f++) {
            int row_l = wm * 32 + f * 16 + g;
            int s = (m0 + row_l) & (SEQ - 1);
#pragma unroll
            for (int j = 0; j < 8; j++) {
                int col_l = wn * 64 + j * 8 + i2;
                float e0 = acc[f][j][0], od0 = acc[f][j][1];
                float e1 = acc[f][j][2], od1 = acc[f][j][3];
                __half2 v0, v1;
                if (sel == 2) {
                    v0 = __floats2half2_rn(e0, od0);
                    v1 = __floats2half2_rn(e1, od1);
                } else {
                    int ii = (col_l & 63) >> 1;
                    float c0 = g_ct[s * 32 + ii],       sn0 = g_st[s * 32 + ii];
                    float c1 = g_ct[(s + 8) * 32 + ii], sn1 = g_st[(s + 8) * 32 + ii];
                    float re0 = e0 * c0 - od0 * sn0, ro0 = od0 * c0 + e0 * sn0;
                    float re1 = e1 * c1 - od1 * sn1, ro1 = od1 * c1 + e1 * sn1;
                    if (sel == 0) {
                        re0 *= QSCALE; ro0 *= QSCALE;
                        re1 *= QSCALE; ro1 *= QSCALE;
                    }
                    v0 = __floats2half2_rn(re0, ro0);
                    v1 = __floats2half2_rn(re1, ro1);
                }
                *(__half2*)&hs[row_l * 136 + col_l] = v0;
                *(__half2*)&hs[(row_l + 8) * 136 + col_l] = v1;
            }
        }
        __syncthreads();
        __half* dstbase = (sel == 0) ? g_qh : (sel == 1) ? g_kh : g_vh;
#pragma unroll
        for (int it = 0; it < 32; it++) {
            int rowid = it * 8 + wid;        // 0..255 = 128 tokens x 2 heads
            int t_l = rowid & 127;
            int hh_l = rowid >> 7;
            __half2 v = ((__half2*)&hs[t_l * 136 + hh_l * 64])[lane];
            int tok = m0 + t_l;
            int s = tok & (SEQ - 1), bb = tok >> 11;
            int hh = (cb >> 6) + hh_l;
            size_t o = ((((size_t)bb * NUM_HEADS + hh) * SEQ + s) * HEAD_DIM) >> 1;
            ((__half2*)dstbase)[o + lane] = v;
        }
    }
}

// ---------------------------------------------------------------------------
// Flash attention (causal) with HMMA. Block = 128 q rows of one (b,h).
// 8 warps, warp = 16 q rows. K-chunk = 128 keys, 2-stage cp.async, 2 CTAs/SM.
// Diagonal chunks skip fully-masked j-blocks per warp (DIAG template).
// smem: Q @0 (16K) | 2 x (K 16K + V 16K) @16384
// ---------------------------------------------------------------------------
#define FSMEM (16384 + 2 * 32768)   // 81920

__device__ __forceinline__ void flash_load_kv(
    uint32_t sb, int tid, int buf, const __half* K0, const __half* V0)
{
    const uint32_t kbase = sb + 16384 + buf * 32768;
#pragma unroll
    for (int u = 0; u < 4; u++) {
        int idx = u * 256 + tid;
        int row = idx >> 3, seg = idx & 7;
        uint32_t d = swz((row << 7) + (seg << 4));
        cp16(kbase + d,         K0 + row * 64 + seg * 8);
        cp16(kbase + 16384 + d, V0 + row * 64 + seg * 8);
    }
}

template<bool DIAG>
__device__ __forceinline__ void flash_chunk(
    uint32_t Kb, uint32_t Vb, const uint32_t (&qa)[4][4],
    float (&oacc)[8][4], float& m0r, float& m1r, float& l0, float& l1,
    int wid, int lane, int g, int i2)
{
    const int fK = DIAG ? (wid + 1) : 8;   // kb f-blocks (2 j each) / PV kk groups

    float sacc[16][4];
#pragma unroll
    for (int j = 0; j < 16; j++) {
        float init = (DIAG && j >= 2 * fK) ? -1e30f : 0.0f;
#pragma unroll
        for (int x = 0; x < 4; x++) sacc[j][x] = init;
    }

#pragma unroll
    for (int kt = 0; kt < 4; kt++) {
        uint32_t kb[16][2];
#pragma unroll
        for (int f = 0; f < 8; f++) {
            if (DIAG && f >= fK) break;
            int nrow = f * 16 + (lane & 7) + ((lane >> 4) & 1) * 8;
            uint32_t r[4];
            ldsm4(r, Kb + swz((nrow << 7) + kt * 32 + (((lane >> 3) & 1) << 4)));
            kb[2 * f][0] = r[0]; kb[2 * f][1] = r[1];
            kb[2 * f + 1][0] = r[2]; kb[2 * f + 1][1] = r[3];
        }
#pragma unroll
        for (int j = 0; j < 16; j++) {
            if (DIAG && j >= 2 * fK) break;
            mma_(sacc[j], qa[kt], kb[j]);
        }
    }

    if (DIAG) {   // causal mask inside computed blocks
#pragma unroll
        for (int j = 0; j < 16; j++) {
            if (j >= 2 * fK) break;
#pragma unroll
            for (int x = 0; x < 4; x++) {
                int col = j * 8 + i2 + (x & 1);
                int row = wid * 16 + g + ((x >> 1) << 3);
                if (col > row) sacc[j][x] = -1e30f;
            }
        }
    }

    // fp32 row max
    float mx0 = -1e30f, mx1 = -1e30f;
#pragma unroll
    for (int j = 0; j < 16; j++) {
        mx0 = fmaxf(mx0, fmaxf(sacc[j][0], sacc[j][1]));
        mx1 = fmaxf(mx1, fmaxf(sacc[j][2], sacc[j][3]));
    }
    mx0 = fmaxf(mx0, __shfl_xor_sync(0xffffffffu, mx0, 1));
    mx0 = fmaxf(mx0, __shfl_xor_sync(0xffffffffu, mx0, 2));
    mx1 = fmaxf(mx1, __shfl_xor_sync(0xffffffffu, mx1, 1));
    mx1 = fmaxf(mx1, __shfl_xor_sync(0xffffffffu, mx1, 2));
    float mn0 = fmaxf(m0r, mx0), mn1 = fmaxf(m1r, mx1);
    float a0 = ex2(m0r - mn0), a1 = ex2(m1r - mn1);
    m0r = mn0; m1r = mn1;
    l0 *= a0; l1 *= a1;
#pragma unroll
    for (int j = 0; j < 8; j++) {
        oacc[j][0] *= a0; oacc[j][1] *= a0;
        oacc[j][2] *= a1; oacc[j][3] *= a1;
    }

    // pack -> hsub -> f16x2 exp; MUFU output doubles as the P fragment
    const __half2 mn0h = __float2half2_rn(mn0);
    const __half2 mn1h = __float2half2_rn(mn1);
    uint32_t Pa[8][4];
    float s0 = 0.0f, s1 = 0.0f;
#pragma unroll
    for (int kk = 0; kk < 8; kk++) {
        if (DIAG && kk >= fK) break;
        __half2 p00 = h2ex2(__hsub2(
            __floats2half2_rn(sacc[2 * kk][0], sacc[2 * kk][1]), mn0h));
        __half2 p10 = h2ex2(__hsub2(
            __floats2half2_rn(sacc[2 * kk + 1][0], sacc[2 * kk + 1][1]), mn0h));
        __half2 p01 = h2ex2(__hsub2(
            __floats2half2_rn(sacc[2 * kk][2], sacc[2 * kk][3]), mn1h));
        __half2 p11 = h2ex2(__hsub2(
            __floats2half2_rn(sacc[2 * kk + 1][2], sacc[2 * kk + 1][3]), mn1h));
        Pa[kk][0] = h2u(p00); Pa[kk][1] = h2u(p01);
        Pa[kk][2] = h2u(p10); Pa[kk][3] = h2u(p11);
        float2 f0 = __half22float2(__hadd2(p00, p10));
        float2 f1 = __half22float2(__hadd2(p01, p11));
        s0 += f0.x + f0.y;
        s1 += f1.x + f1.y;
    }
    l0 += s0; l1 += s1;

    // O += P V
#pragma unroll
    for (int kk = 0; kk < 8; kk++) {
        if (DIAG && kk >= fK) break;
        uint32_t vb[8][2];
#pragma unroll
        for (int f = 0; f < 4; f++) {
            int krow = kk * 16 + (lane & 7) + ((lane >> 3) & 1) * 8;
            int dcol = f * 16 + ((lane >> 4) & 1) * 8;
            uint32_t r[4];
            ldsm4t(r, Vb + swz((krow << 7) + dcol * 2));
            vb[2 * f][0] = r[0]; vb[2 * f][1] = r[1];
            vb[2 * f + 1][0] = r[2]; vb[2 * f + 1][1] = r[3];
        }
#pragma unroll
        for (int j = 0; j < 8; j++) mma_(oacc[j], Pa[kk], vb[j]);
    }
}

__global__ __launch_bounds__(256, 2) void flash_attn_tc()
{
    extern __shared__ char smraw[];
    const uint32_t sb = smem_u32(smraw);
    const int tid = threadIdx.x;
    const int wid = tid >> 5, lane = tid & 31;
    const int qt = (int)gridDim.x - 1 - (int)blockIdx.x;   // heavy tiles first
    const int h = blockIdx.y, b = blockIdx.z;

    const size_t bh = ((size_t)b * NUM_HEADS + h) * SEQ * HEAD_DIM;
    const __half* Qg = g_qh + bh + (size_t)qt * 128 * 64;
    const __half* Kg = g_kh + bh;
    const __half* Vg = g_vh + bh;

    // Q tile load
#pragma unroll
    for (int u = 0; u < 4; u++) {
        int idx = u * 256 + tid;
        int row = idx >> 3, seg = idx & 7;
        cp16(sb + swz((row << 7) + (seg << 4)), Qg + row * 64 + seg * 8);
    }
    CP_COMMIT();
    flash_load_kv(sb, tid, 0, Kg, Vg);
    CP_COMMIT();
    CP_WAIT(1);               // Q ready
    __syncthreads();

    // hoist Q fragments
    uint32_t qa[4][4];
#pragma unroll
    for (int kt = 0; kt < 4; kt++) {
        int mrow = wid * 16 + (lane & 7) + ((lane >> 3) & 1) * 8;
        ldsm4(qa[kt], sb + swz((mrow << 7) + kt * 32 + ((lane >> 4) << 4)));
    }

    float oacc[8][4];
#pragma unroll
    for (int j = 0; j < 8; j++)
#pragma unroll
        for (int x = 0; x < 4; x++) oacc[j][x] = 0.0f;
    float m0r = -1e30f, m1r = -1e30f, l0 = 0.0f, l1 = 0.0f;
    const int g = lane >> 2, i2 = (lane & 3) * 2;

    for (int jt = 0; jt <= qt; jt++) {
        const int buf = jt & 1;
        if (jt < qt) {
            flash_load_kv(sb, tid, buf ^ 1,
                          Kg + (size_t)(jt + 1) * 128 * 64,
                          Vg + (size_t)(jt + 1) * 128 * 64);
            CP_COMMIT();
            CP_WAIT(1);
        } else {
            CP_WAIT(0);
        }
        __syncthreads();
        const uint32_t Kb = sb + 16384 + buf * 32768;
        const uint32_t Vb = Kb + 16384;

        if (jt == qt)
            flash_chunk<true >(Kb, Vb, qa, oacc, m0r, m1r, l0, l1, wid, lane, g, i2);
        else
            flash_chunk<false>(Kb, Vb, qa, oacc, m0r, m1r, l0, l1, wid, lane, g, i2);
        __syncthreads();
    }

    // final row-sum reduce and write (fp16, feeds the out-projection)
    l0 += __shfl_xor_sync(0xffffffffu, l0, 1);
    l0 += __shfl_xor_sync(0xffffffffu, l0, 2);
    l1 += __shfl_xor_sync(0xffffffffu, l1, 1);
    l1 += __shfl_xor_sync(0xffffffffu, l1, 2);
    float inv0 = 1.0f / l0, inv1 = 1.0f / l1;

    int tok0 = b * SEQ + qt * 128 + wid * 16 + g;
#pragma unroll
    for (int j = 0; j < 8; j++) {
        int col = h * 64 + j * 8 + i2;
        *(__half2*)&g_aoh[(size_t)tok0 * D_MODEL + col] =
            __floats2half2_rn(oacc[j][0] * inv0, oacc[j][1] * inv0);
        *(__half2*)&g_aoh[(size_t)(tok0 + 8) * D_MODEL + col] =
            __floats2half2_rn(oacc[j][2] * inv1, oacc[j][3] * inv1);
    }
}

// ---------------------------------------------------------------------------
extern "C" void kernel_launch(void* const* d_in, const int* in_sizes, int n_in,
                              void* d_out, int out_size)
{
    (void)in_sizes; (void)n_in; (void)out_size;
    const float* x      = (const float*)d_in[0];
    const float* w_qkv  = (const float*)d_in[1];
    const float* w_o    = (const float*)d_in[2];
    const int*   pos    = (const int*)d_in[3];
    float*       out    = (float*)d_out;

    __half *xh, *wqh, *woh, *aoh;
    cudaGetSymbolAddress((void**)&xh,  g_xh);
    cudaGetSymbolAddress((void**)&wqh, g_wqh);
    cudaGetSymbolAddress((void**)&woh, g_woh);
    cudaGetSymbolAddress((void**)&aoh, g_aoh);

    cudaFuncSetAttribute(gemm_tc<0>,
                         cudaFuncAttributeMaxDynamicSharedMemorySize, NSTG * STAGE);
    cudaFuncSetAttribute(gemm_tc<1>,
                         cudaFuncAttributeMaxDynamicSharedMemorySize, NSTG * STAGE);
    cudaFuncSetAttribute(flash_attn_tc,
                         cudaFuncAttributeMaxDynamicSharedMemorySize, FSMEM);

    rope_table_kernel<<<SEQ * 32 / 256, 256>>>(pos);
    conv_all_kernel<<<N4_ALL / 256, 256>>>(x, w_qkv, w_o);

    // QKV projection with fused RoPE/split/transpose epilogue
    gemm_tc<1><<<dim3(3 * D_MODEL / 128, TOKENS / 128), 256, NSTG * STAGE>>>(
        xh, wqh, nullptr, 3 * D_MODEL);

    flash_attn_tc<<<dim3(SEQ / 128, NUM_HEADS, BATCH), 256, FSMEM>>>();

    // output projection -> fp32 out
    gemm_tc<0><<<dim3(D_MODEL / 128, TOKENS / 128), 256, NSTG * STAGE>>>(
        aoh, woh, out, D_MODEL);
}

// round 13
// speedup vs baseline: 1.1039x; 1.1039x over previous
#include <cuda_runtime.h>
#include <cuda_fp16.h>
#include <math.h>
#include <stdint.h>

#define D_MODEL   1024
#define NUM_HEADS 16
#define HEAD_DIM  64
#define BATCH     2
#define SEQ       2048
#define TOKENS    (BATCH * SEQ)      // 4096
#define QSCALE    (0.125f * 1.44269504f)

// ---------------- scratch (device globals; no allocation allowed) ----------
__device__ __align__(16) __half g_qh[TOKENS * D_MODEL];   // [b,h,s,d], pre-scaled
__device__ __align__(16) __half g_kh[TOKENS * D_MODEL];
__device__ __align__(16) __half g_vh[TOKENS * D_MODEL];
__device__ __align__(16) float  g_ct[SEQ * 32];
__device__ __align__(16) float  g_st[SEQ * 32];
__device__ __align__(16) __half g_xh[TOKENS * D_MODEL];
__device__ __align__(16) __half g_wqh[3 * D_MODEL * D_MODEL];
__device__ __align__(16) __half g_woh[D_MODEL * D_MODEL];
__device__ __align__(16) __half g_aoh[TOKENS * D_MODEL];

// ---------------------------------------------------------------------------
// helpers
// ---------------------------------------------------------------------------
__device__ __forceinline__ uint32_t smem_u32(const void* p) {
    uint32_t a;
    asm("{ .reg .u64 t; cvta.to.shared.u64 t, %1; cvt.u32.u64 %0, t; }" : "=r"(a) : "l"(p));
    return a;
}
__device__ __forceinline__ void cp16(uint32_t dst, const void* src) {
    asm volatile("cp.async.cg.shared.global [%0], [%1], 16;" :: "r"(dst), "l"(src));
}
#define CP_COMMIT() asm volatile("cp.async.commit_group;")
#define CP_WAIT(n)  asm volatile("cp.async.wait_group %0;" :: "n"(n))

__device__ __forceinline__ void ldsm4(uint32_t* r, uint32_t a) {
    asm volatile("ldmatrix.sync.aligned.m8n8.x4.shared.b16 {%0,%1,%2,%3}, [%4];"
                 : "=r"(r[0]), "=r"(r[1]), "=r"(r[2]), "=r"(r[3]) : "r"(a));
}
__device__ __forceinline__ void ldsm4t(uint32_t* r, uint32_t a) {
    asm volatile("ldmatrix.sync.aligned.m8n8.x4.trans.shared.b16 {%0,%1,%2,%3}, [%4];"
                 : "=r"(r[0]), "=r"(r[1]), "=r"(r[2]), "=r"(r[3]) : "r"(a));
}
__device__ __forceinline__ void mma_(float* c, const uint32_t* a, const uint32_t* b) {
    asm volatile(
        "mma.sync.aligned.m16n8k16.row.col.f32.f16.f16.f32 "
        "{%0,%1,%2,%3}, {%4,%5,%6,%7}, {%8,%9}, {%0,%1,%2,%3};"
        : "+f"(c[0]), "+f"(c[1]), "+f"(c[2]), "+f"(c[3])
        : "r"(a[0]), "r"(a[1]), "r"(a[2]), "r"(a[3]), "r"(b[0]), "r"(b[1]));
}
__device__ __forceinline__ uint32_t swz(uint32_t o) { return o ^ ((o >> 3) & 0x70); }
__device__ __forceinline__ float ex2(float x) {
    float r; asm("ex2.approx.ftz.f32 %0, %1;" : "=f"(r) : "f"(x)); return r;
}
__device__ __forceinline__ __half2 h2ex2(__half2 x) {
    uint32_t xi = *(uint32_t*)&x, ri;
    asm("ex2.approx.f16x2 %0, %1;" : "=r"(ri) : "r"(xi));
    return *(__half2*)&ri;
}
__device__ __forceinline__ uint32_t h2u(__half2 h) { return *(uint32_t*)&h; }

// ---------------------------------------------------------------------------
// merged fp32 -> fp16 conversion for x, w_qkv, w_o (one launch)
// ---------------------------------------------------------------------------
#define N4_X  (TOKENS * D_MODEL / 4)
#define N4_WQ (3 * D_MODEL * D_MODEL / 4)
#define N4_WO (D_MODEL * D_MODEL / 4)
#define N4_ALL (N4_X + N4_WQ + N4_WO)

__global__ __launch_bounds__(256) void conv_all_kernel(
    const float* __restrict__ x, const float* __restrict__ wq,
    const float* __restrict__ wo)
{
    int i = blockIdx.x * 256 + threadIdx.x;
    const float* src; __half* dst; int off;
    if (i < N4_X)              { src = x;  dst = g_xh;  off = i; }
    else if (i < N4_X + N4_WQ) { src = wq; dst = g_wqh; off = i - N4_X; }
    else                       { src = wo; dst = g_woh; off = i - N4_X - N4_WQ; }
    float4 v = ((const float4*)src)[off];
    __half2* h2 = (__half2*)dst;
    h2[2 * off]     = __floats2half2_rn(v.x, v.y);
    h2[2 * off + 1] = __floats2half2_rn(v.z, v.w);
}

// ---------------------------------------------------------------------------
// RoPE tables (fp64 trig)
// ---------------------------------------------------------------------------
__global__ void rope_table_kernel(const int* __restrict__ pos)
{
    int idx = blockIdx.x * 256 + threadIdx.x;
    if (idx >= SEQ * 32) return;
    int s = idx >> 5, i = idx & 31;
    double f = (double)pos[s] * pow(10000.0, -(double)i / 32.0);
    g_ct[idx] = (float)cos(f);
    g_st[idx] = (float)sin(f);
}

// ---------------------------------------------------------------------------
// HMMA fp16 NT GEMM: C[M,N] = A[M,K] B[N,K]^T, K=1024, fp32 accum.
// 128x128 tile, BK=64, 8 warps, 3-stage cp.async pipeline, 2 CTAs/SM.
// MODE 0: fp32 C out. MODE 1: fused RoPE+split -> g_qh/g_kh/g_vh.
// (direct stores — R11 form; R12's staged epilogue reverted with the rest)
// ---------------------------------------------------------------------------
#define GK 1024
#define STAGE 32768   // A 16K | B 16K
#define NSTG  3

__device__ __forceinline__ void gemm_load_stage(
    uint32_t base, int tid, int m0, int n0, int c0,
    const __half* A, const __half* B)
{
#pragma unroll
    for (int u = 0; u < 4; u++) {
        int idx = u * 256 + tid;          // 0..1023
        int row = idx >> 3, seg = idx & 7;
        uint32_t d = swz((row << 7) + (seg << 4));
        cp16(base + d,         A + (size_t)(m0 + row) * GK + c0 + seg * 8);
        cp16(base + 16384 + d, B + (size_t)(n0 + row) * GK + c0 + seg * 8);
    }
}

template<int MODE>
__global__ __launch_bounds__(256, 2) void gemm_tc(
    const __half* __restrict__ A, const __half* __restrict__ B,
    float* __restrict__ Cout, int N)
{
    extern __shared__ char smraw[];
    const uint32_t sb = smem_u32(smraw);
    const int tid = threadIdx.x;
    const int wid = tid >> 5, lane = tid & 31;
    const int wm = wid & 3, wn = wid >> 2;
    const int m0 = blockIdx.y << 7, n0 = blockIdx.x << 7;

    float acc[2][8][4];
#pragma unroll
    for (int f = 0; f < 2; f++)
#pragma unroll
        for (int j = 0; j < 8; j++)
#pragma unroll
            for (int x = 0; x < 4; x++) acc[f][j][x] = 0.0f;

#pragma unroll
    for (int p = 0; p < NSTG - 1; p++) {
        gemm_load_stage(sb + p * STAGE, tid, m0, n0, p * 64, A, B);
        CP_COMMIT();
    }

    for (int c = 0; c < 16; c++) {
        if (c < 15) CP_WAIT(1); else CP_WAIT(0);
        __syncthreads();
        if (c + NSTG - 1 < 16) {
            gemm_load_stage(sb + ((c + NSTG - 1) % NSTG) * STAGE, tid, m0, n0,
                            (c + NSTG - 1) * 64, A, B);
            CP_COMMIT();
        }
        const uint32_t base = sb + (c % NSTG) * STAGE;

#pragma unroll
        for (int kt = 0; kt < 4; kt++) {
            uint32_t ah[2][4];
#pragma unroll
            for (int f = 0; f < 2; f++) {
                int mrow = wm * 32 + f * 16 + (lane & 7) + ((lane >> 3) & 1) * 8;
                ldsm4(ah[f], base + swz((mrow << 7) + kt * 32 + ((lane >> 4) << 4)));
            }
            uint32_t bh[8][2];
#pragma unroll
            for (int f = 0; f < 4; f++) {
                int nrow = wn * 64 + f * 16 + (lane & 7) + ((lane >> 4) & 1) * 8;
                uint32_t r[4];
                ldsm4(r, base + 16384 +
                         swz((nrow << 7) + kt * 32 + (((lane >> 3) & 1) << 4)));
                bh[2 * f][0] = r[0]; bh[2 * f][1] = r[1];
                bh[2 * f + 1][0] = r[2]; bh[2 * f + 1][1] = r[3];
            }
#pragma unroll
            for (int f = 0; f < 2; f++)
#pragma unroll
                for (int j = 0; j < 8; j++) mma_(acc[f][j], ah[f], bh[j]);
        }
    }

    const int g = lane >> 2, i2 = (lane & 3) * 2;

    if (MODE == 0) {
#pragma unroll
        for (int f = 0; f < 2; f++)
#pragma unroll
            for (int j = 0; j < 8; j++) {
                int row = m0 + wm * 32 + f * 16 + g;
                int col = n0 + wn * 64 + j * 8 + i2;
                *(float2*)&Cout[(size_t)row * N + col] =
                    make_float2(acc[f][j][0], acc[f][j][1]);
                *(float2*)&Cout[(size_t)(row + 8) * N + col] =
                    make_float2(acc[f][j][2], acc[f][j][3]);
            }
    } else {
        // fused RoPE + head-split + transpose epilogue.
        const int sel  = n0 >> 10;               // 0=q, 1=k, 2=v
        const int csec = (n0 & 1023) + wn * 64;
#pragma unroll
        for (int f = 0; f < 2; f++) {
            int row = m0 + wm * 32 + f * 16 + g;     // token
            int s = row & (SEQ - 1), b = row >> 11;
#pragma unroll
            for (int j = 0; j < 8; j++) {
                int col = csec + j * 8 + i2;
                int hh = col >> 6, d = col & 63, ii = d >> 1;
                size_t o1 = ((((size_t)b * NUM_HEADS + hh) * SEQ + s) * HEAD_DIM + d) >> 1;
                size_t o2 = o1 + 8 * HEAD_DIM / 2;   // token row+8
                float e0 = acc[f][j][0], od0 = acc[f][j][1];
                float e1 = acc[f][j][2], od1 = acc[f][j][3];
                if (sel == 2) {
                    ((__half2*)g_vh)[o1] = __floats2half2_rn(e0, od0);
                    ((__half2*)g_vh)[o2] = __floats2half2_rn(e1, od1);
                } else {
                    float c0 = g_ct[s * 32 + ii],       sn0 = g_st[s * 32 + ii];
                    float c1 = g_ct[(s + 8) * 32 + ii], sn1 = g_st[(s + 8) * 32 + ii];
                    float re0 = e0 * c0 - od0 * sn0, ro0 = od0 * c0 + e0 * sn0;
                    float re1 = e1 * c1 - od1 * sn1, ro1 = od1 * c1 + e1 * sn1;
                    if (sel == 0) {
                        ((__half2*)g_qh)[o1] =
                            __floats2half2_rn(re0 * QSCALE, ro0 * QSCALE);
                        ((__half2*)g_qh)[o2] =
                            __floats2half2_rn(re1 * QSCALE, ro1 * QSCALE);
                    } else {
                        ((__half2*)g_kh)[o1] = __floats2half2_rn(re0, ro0);
                        ((__half2*)g_kh)[o2] = __floats2half2_rn(re1, ro1);
                    }
                }
            }
        }
    }
}

// ---------------------------------------------------------------------------
// Flash attention (causal) with HMMA. Block = 128 q rows of one (b,h).
// 8 warps, warp = 16 q rows. K-chunk = 128 keys, 2-stage cp.async pipeline,
// 2 CTAs/SM (80KB smem, <=128 regs). Scores pre-scaled via Q.  (R11 form)
// smem: Q @0 (16K) | 2 x (K 16K + V 16K) @16384
// ---------------------------------------------------------------------------
#define FSMEM (16384 + 2 * 32768)   // 81920

__device__ __forceinline__ void flash_load_kv(
    uint32_t sb, int tid, int buf, const __half* K0, const __half* V0)
{
    const uint32_t kbase = sb + 16384 + buf * 32768;
#pragma unroll
    for (int u = 0; u < 4; u++) {
        int idx = u * 256 + tid;
        int row = idx >> 3, seg = idx & 7;
        uint32_t d = swz((row << 7) + (seg << 4));
        cp16(kbase + d,         K0 + row * 64 + seg * 8);
        cp16(kbase + 16384 + d, V0 + row * 64 + seg * 8);
    }
}

__global__ __launch_bounds__(256, 2) void flash_attn_tc()
{
    extern __shared__ char smraw[];
    const uint32_t sb = smem_u32(smraw);
    const int tid = threadIdx.x;
    const int wid = tid >> 5, lane = tid & 31;
    const int qt = (int)gridDim.x - 1 - (int)blockIdx.x;   // heavy tiles first
    const int h = blockIdx.y, b = blockIdx.z;

    const size_t bh = ((size_t)b * NUM_HEADS + h) * SEQ * HEAD_DIM;
    const __half* Qg = g_qh + bh + (size_t)qt * 128 * 64;
    const __half* Kg = g_kh + bh;
    const __half* Vg = g_vh + bh;

    // Q tile load
#pragma unroll
    for (int u = 0; u < 4; u++) {
        int idx = u * 256 + tid;
        int row = idx >> 3, seg = idx & 7;
        cp16(sb + swz((row << 7) + (seg << 4)), Qg + row * 64 + seg * 8);
    }
    CP_COMMIT();
    flash_load_kv(sb, tid, 0, Kg, Vg);
    CP_COMMIT();
    CP_WAIT(1);               // Q ready
    __syncthreads();

    // hoist Q fragments
    uint32_t qa[4][4];
#pragma unroll
    for (int kt = 0; kt < 4; kt++) {
        int mrow = wid * 16 + (lane & 7) + ((lane >> 3) & 1) * 8;
        ldsm4(qa[kt], sb + swz((mrow << 7) + kt * 32 + ((lane >> 4) << 4)));
    }

    float oacc[8][4];
#pragma unroll
    for (int j = 0; j < 8; j++)
#pragma unroll
        for (int x = 0; x < 4; x++) oacc[j][x] = 0.0f;
    float m0r = -1e30f, m1r = -1e30f, l0 = 0.0f, l1 = 0.0f;
    const int g = lane >> 2, i2 = (lane & 3) * 2;

    for (int jt = 0; jt <= qt; jt++) {
        const int buf = jt & 1;
        if (jt < qt) {
            flash_load_kv(sb, tid, buf ^ 1,
                          Kg + (size_t)(jt + 1) * 128 * 64,
                          Vg + (size_t)(jt + 1) * 128 * 64);
            CP_COMMIT();
            CP_WAIT(1);
        } else {
            CP_WAIT(0);
        }
        __syncthreads();
        const uint32_t Kb = sb + 16384 + buf * 32768;
        const uint32_t Vb = Kb + 16384;

        // S = Q K^T  (m16 x n128 per warp), log2-domain units
        float sacc[16][4];
#pragma unroll
        for (int j = 0; j < 16; j++)
#pragma unroll
            for (int x = 0; x < 4; x++) sacc[j][x] = 0.0f;

#pragma unroll
        for (int kt = 0; kt < 4; kt++) {
            uint32_t kb[16][2];
#pragma unroll
            for (int f = 0; f < 8; f++) {
                int nrow = f * 16 + (lane & 7) + ((lane >> 4) & 1) * 8;
                uint32_t r[4];
                ldsm4(r, Kb + swz((nrow << 7) + kt * 32 + (((lane >> 3) & 1) << 4)));
                kb[2 * f][0] = r[0]; kb[2 * f][1] = r[1];
                kb[2 * f + 1][0] = r[2]; kb[2 * f + 1][1] = r[3];
            }
#pragma unroll
            for (int j = 0; j < 16; j++) mma_(sacc[j], qa[kt], kb[j]);
        }

        if (jt == qt) {   // causal mask on diagonal tile
#pragma unroll
            for (int j = 0; j < 16; j++)
#pragma unroll
                for (int x = 0; x < 4; x++) {
                    int col = j * 8 + i2 + (x & 1);
                    int row = wid * 16 + g + ((x >> 1) << 3);
                    if (col > row) sacc[j][x] = -1e30f;
                }
        }

        // fp32 row max
        float mx0 = -1e30f, mx1 = -1e30f;
#pragma unroll
        for (int j = 0; j < 16; j++) {
            mx0 = fmaxf(mx0, fmaxf(sacc[j][0], sacc[j][1]));
            mx1 = fmaxf(mx1, fmaxf(sacc[j][2], sacc[j][3]));
        }
        mx0 = fmaxf(mx0, __shfl_xor_sync(0xffffffffu, mx0, 1));
        mx0 = fmaxf(mx0, __shfl_xor_sync(0xffffffffu, mx0, 2));
        mx1 = fmaxf(mx1, __shfl_xor_sync(0xffffffffu, mx1, 1));
        mx1 = fmaxf(mx1, __shfl_xor_sync(0xffffffffu, mx1, 2));
        float mn0 = fmaxf(m0r, mx0), mn1 = fmaxf(m1r, mx1);
        float a0 = ex2(m0r - mn0), a1 = ex2(m1r - mn1);
        m0r = mn0; m1r = mn1;
        l0 *= a0; l1 *= a1;
#pragma unroll
        for (int j = 0; j < 8; j++) {
            oacc[j][0] *= a0; oacc[j][1] *= a0;
            oacc[j][2] *= a1; oacc[j][3] *= a1;
        }

        // pack -> hsub -> f16x2 exp; MUFU output doubles as the P fragment
        const __half2 mn0h = __float2half2_rn(mn0);
        const __half2 mn1h = __float2half2_rn(mn1);
        uint32_t Pa[8][4];
        float s0 = 0.0f, s1 = 0.0f;
#pragma unroll
        for (int kk = 0; kk < 8; kk++) {
            __half2 p00 = h2ex2(__hsub2(
                __floats2half2_rn(sacc[2 * kk][0], sacc[2 * kk][1]), mn0h));
            __half2 p10 = h2ex2(__hsub2(
                __floats2half2_rn(sacc[2 * kk + 1][0], sacc[2 * kk + 1][1]), mn0h));
            __half2 p01 = h2ex2(__hsub2(
                __floats2half2_rn(sacc[2 * kk][2], sacc[2 * kk][3]), mn1h));
            __half2 p11 = h2ex2(__hsub2(
                __floats2half2_rn(sacc[2 * kk + 1][2], sacc[2 * kk + 1][3]), mn1h));
            Pa[kk][0] = h2u(p00); Pa[kk][1] = h2u(p01);
            Pa[kk][2] = h2u(p10); Pa[kk][3] = h2u(p11);
            float2 f0 = __half22float2(__hadd2(p00, p10));
            float2 f1 = __half22float2(__hadd2(p01, p11));
            s0 += f0.x + f0.y;
            s1 += f1.x + f1.y;
        }
        l0 += s0; l1 += s1;

        // O += P V   (V fragments via ldmatrix.trans)
#pragma unroll
        for (int kk = 0; kk < 8; kk++) {
            uint32_t vb[8][2];
#pragma unroll
            for (int f = 0; f < 4; f++) {
                int krow = kk * 16 + (lane & 7) + ((lane >> 3) & 1) * 8;
                int dcol = f * 16 + ((lane >> 4) & 1) * 8;
                uint32_t r[4];
                ldsm4t(r, Vb + swz((krow << 7) + dcol * 2));
                vb[2 * f][0] = r[0]; vb[2 * f][1] = r[1];
                vb[2 * f + 1][0] = r[2]; vb[2 * f + 1][1] = r[3];
            }
#pragma unroll
            for (int j = 0; j < 8; j++) mma_(oacc[j], Pa[kk], vb[j]);
        }
        __syncthreads();
    }

    // final row-sum reduce and write (fp16, feeds the out-projection)
    l0 += __shfl_xor_sync(0xffffffffu, l0, 1);
    l0 += __shfl_xor_sync(0xffffffffu, l0, 2);
    l1 += __shfl_xor_sync(0xffffffffu, l1, 1);
    l1 += __shfl_xor_sync(0xffffffffu, l1, 2);
    float inv0 = 1.0f / l0, inv1 = 1.0f / l1;

    int tok0 = b * SEQ + qt * 128 + wid * 16 + g;
#pragma unroll
    for (int j = 0; j < 8; j++) {
        int col = h * 64 + j * 8 + i2;
        *(__half2*)&g_aoh[(size_t)tok0 * D_MODEL + col] =
            __floats2half2_rn(oacc[j][0] * inv0, oacc[j][1] * inv0);
        *(__half2*)&g_aoh[(size_t)(tok0 + 8) * D_MODEL + col] =
            __floats2half2_rn(oacc[j][2] * inv1, oacc[j][3] * inv1);
    }
}

// ---------------------------------------------------------------------------
extern "C" void kernel_launch(void* const* d_in, const int* in_sizes, int n_in,
                              void* d_out, int out_size)
{
    (void)in_sizes; (void)n_in; (void)out_size;
    const float* x      = (const float*)d_in[0];
    const float* w_qkv  = (const float*)d_in[1];
    const float* w_o    = (const float*)d_in[2];
    const int*   pos    = (const int*)d_in[3];
    float*       out    = (float*)d_out;

    __half *xh, *wqh, *woh, *aoh;
    cudaGetSymbolAddress((void**)&xh,  g_xh);
    cudaGetSymbolAddress((void**)&wqh, g_wqh);
    cudaGetSymbolAddress((void**)&woh, g_woh);
    cudaGetSymbolAddress((void**)&aoh, g_aoh);

    cudaFuncSetAttribute(gemm_tc<0>,
                         cudaFuncAttributeMaxDynamicSharedMemorySize, NSTG * STAGE);
    cudaFuncSetAttribute(gemm_tc<1>,
                         cudaFuncAttributeMaxDynamicSharedMemorySize, NSTG * STAGE);
    cudaFuncSetAttribute(flash_attn_tc,
                         cudaFuncAttributeMaxDynamicSharedMemorySize, FSMEM);

    rope_table_kernel<<<SEQ * 32 / 256, 256>>>(pos);
    conv_all_kernel<<<N4_ALL / 256, 256>>>(x, w_qkv, w_o);

    // QKV projection with fused RoPE/split/transpose epilogue
    gemm_tc<1><<<dim3(3 * D_MODEL / 128, TOKENS / 128), 256, NSTG * STAGE>>>(
        xh, wqh, nullptr, 3 * D_MODEL);

    flash_attn_tc<<<dim3(SEQ / 128, NUM_HEADS, BATCH), 256, FSMEM>>>();

    // output projection -> fp32 out
    gemm_tc<0><<<dim3(D_MODEL / 128, TOKENS / 128), 256, NSTG * STAGE>>>(
        aoh, woh, out, D_MODEL);
}